// round 3
// baseline (speedup 1.0000x reference)
#include <cuda_runtime.h>

// Problem constants
#define Nn 8
#define Cc 256
#define Tt 1024
#define Vv 25
#define Hh 8
#define Dd 64
#define HC 512   // Hh * Dd

// SMEM paddings
#define FPAD 26   // feature rows (8B aligned rows)
#define VPAD 29   // v rows
#define ZPAD 28   // z rows (16B aligned rows)
#define APAD 28   // attn rows (16B aligned rows)
#define W1PAD 65  // WvT rows (conflict-free)
#define W2PAD 33  // Wo chunk rows (conflict-free)
#define W2BUF (Cc * W2PAD)   // 8448 floats per buffer

typedef unsigned long long u64;

__device__ float g_q[HC * Vv];
__device__ float g_k[HC * Vv];
__device__ float g_attn[Hh * Vv * Vv];

// ---------------- packed fp32x2 helpers (sm_100+) ----------------
__device__ __forceinline__ u64 pack2(float x) {
    u64 r; asm("mov.b64 %0, {%1, %1};" : "=l"(r) : "f"(x)); return r;
}
__device__ __forceinline__ u64 ffma2(u64 a, u64 b, u64 c) {
    u64 d; asm("fma.rn.f32x2 %0, %1, %2, %3;" : "=l"(d) : "l"(a), "l"(b), "l"(c));
    return d;
}
__device__ __forceinline__ void unpack2(u64 a, float& lo, float& hi) {
    asm("mov.b64 {%0, %1}, %2;" : "=f"(lo), "=f"(hi) : "l"(a));
}
__device__ __forceinline__ void lds128_u64(u64& a, u64& b, const float* p) {
    unsigned ad = (unsigned)__cvta_generic_to_shared(p);
    asm volatile("ld.shared.v2.u64 {%0, %1}, [%2];" : "=l"(a), "=l"(b) : "r"(ad));
}
__device__ __forceinline__ u64 lds64_u64(const float* p) {
    unsigned ad = (unsigned)__cvta_generic_to_shared(p);
    u64 a; asm volatile("ld.shared.u64 %0, [%1];" : "=l"(a) : "r"(ad)); return a;
}
__device__ __forceinline__ void sts64(float* p, u64 v) {
    unsigned ad = (unsigned)__cvta_generic_to_shared(p);
    asm volatile("st.shared.u64 [%0], %1;" :: "r"(ad), "l"(v));
}

// ---------------------------------------------------------------------------
// Kernel 1: q = Wq @ tf + bq, k = Wk @ tf + bk. One output per thread.
// grid = 100 blocks x 256 threads = 25600 outputs.
// ---------------------------------------------------------------------------
__global__ void qk_kernel(const float* __restrict__ tf,
                          const float* __restrict__ Wq, const float* __restrict__ bq,
                          const float* __restrict__ Wk, const float* __restrict__ bk) {
    extern __shared__ float tf_s[];  // 512*25 floats
    for (int idx = threadIdx.x; idx < HC * Vv; idx += blockDim.x) tf_s[idx] = tf[idx];
    __syncthreads();

    int g = blockIdx.x * blockDim.x + threadIdx.x;
    int which = (g >= HC * Vv) ? 1 : 0;
    int r = which ? (g - HC * Vv) : g;
    int hc = r / Vv;
    int u = r - hc * Vv;
    const float* wrow = (which ? Wk : Wq) + hc * 512;
    float acc = which ? bk[hc] : bq[hc];
#pragma unroll 8
    for (int i = 0; i < 512; i++) acc += wrow[i] * tf_s[i * Vv + u];
    if (which) g_k[r] = acc; else g_q[r] = acc;
}

// ---------------------------------------------------------------------------
// Kernel 2: energy + softmax -> g_attn  (tiny, one block)
// ---------------------------------------------------------------------------
__global__ void attn_kernel() {
    extern __shared__ float s[];
    float* q_s = s;
    float* k_s = s + HC * Vv;
    for (int idx = threadIdx.x; idx < HC * Vv; idx += blockDim.x) {
        q_s[idx] = g_q[idx];
        k_s[idx] = g_k[idx];
    }
    __syncthreads();

    int r = threadIdx.x;  // one thread per (h,u)
    if (r < Hh * Vv) {
        int h = r / Vv;
        int u = r - h * Vv;
        float e[Vv];
#pragma unroll
        for (int j = 0; j < Vv; j++) e[j] = 0.f;
        const float* qb = q_s + h * Dd * Vv;
        const float* kb = k_s + h * Dd * Vv;
        for (int c = 0; c < Dd; c++) {
            float qv = qb[c * Vv + u];
#pragma unroll
            for (int j = 0; j < Vv; j++) e[j] += qv * kb[c * Vv + j];
        }
        float m = -1e30f;
#pragma unroll
        for (int j = 0; j < Vv; j++) { e[j] *= 0.125f; m = fmaxf(m, e[j]); }
        float ssum = 0.f;
#pragma unroll
        for (int j = 0; j < Vv; j++) { e[j] = expf(e[j] - m); ssum += e[j]; }
        float inv = 1.f / ssum;
        float* arow = g_attn + (h * Vv + u) * Vv;
#pragma unroll
        for (int j = 0; j < Vv; j++) arow[j] = e[j] * inv;
    }
}

// ---------------------------------------------------------------------------
// Kernel 3 (main): one block per (n,t). fp32x2 packed math + double-buffered Wo.
// ---------------------------------------------------------------------------
__global__ void __launch_bounds__(256, 1)
main_kernel(const float* __restrict__ f, const float* __restrict__ Wv,
            const float* __restrict__ bv, const float* __restrict__ Wo,
            const float* __restrict__ bo, float* __restrict__ out) {
    extern __shared__ float s[];
    float* f_s    = s;                          // 6656
    float* v_s    = f_s + Cc * FPAD;            // 1856  (@6656)
    float* z_s    = v_s + Dd * VPAD;            // 14336 (@8512, 16B aligned)
    float* attn_s = z_s + HC * ZPAD;            // 5600  (@22848, 16B aligned)
    float* w_s    = attn_s + Hh * Vv * APAD;    // union: WvT (256*65) / Wo dbl-buf (2*8448)

    const int tid = threadIdx.x;
    const int b = blockIdx.x;
    const int n = b >> 10;          // Tt = 1024
    const int t = b & (Tt - 1);

    const float* fbase = f + (size_t)n * (Cc * Tt * Vv) + (size_t)t * Vv;

    // --- stage 0: cooperative loads ---
    for (int idx = tid; idx < Cc * Vv; idx += 256) {
        int i = idx / Vv;
        int u = idx - i * Vv;
        f_s[i * FPAD + u] = fbase[(size_t)i * (Tt * Vv) + u];
    }
    // Wv transposed into union region: w_s[i*W1PAD + c] = Wv[c,i]
    for (int idx = tid; idx < Dd * Cc; idx += 256) {
        int c = idx >> 8;
        int i = idx & 255;
        w_s[i * W1PAD + c] = Wv[idx];
    }
    // attn with padded rows
    for (int idx = tid; idx < Hh * Vv * Vv; idx += 256) {
        int row = idx / Vv;
        int col = idx - row * Vv;
        attn_s[row * APAD + col] = g_attn[idx];
    }
    __syncthreads();

    // --- stage 1: v[c,u] = bv[c] + sum_i Wv[c,i] * f[i,u]  (fp32x2) ---
    {
        int c = tid >> 2;        // 0..63
        int q = tid & 3;         // u block: q*8 .. q*8+7 (q==3 only u=24 valid)
        u64 acc0 = 0, acc1 = 0, acc2 = 0, acc3 = 0;
        const int ub = q * 8;
        for (int i = 0; i < Cc; i++) {
            float w = w_s[i * W1PAD + c];
            u64 w2 = pack2(w);
            const float* fr = f_s + i * FPAD + ub;
            u64 f0 = lds64_u64(fr);
            u64 f1 = lds64_u64(fr + 2);
            u64 f2 = lds64_u64(fr + 4);
            u64 f3 = lds64_u64(fr + 6);
            acc0 = ffma2(w2, f0, acc0);
            acc1 = ffma2(w2, f1, acc1);
            acc2 = ffma2(w2, f2, acc2);
            acc3 = ffma2(w2, f3, acc3);
        }
        float bb = bv[c];
        float lo, hi;
        u64 accs[4] = {acc0, acc1, acc2, acc3};
#pragma unroll
        for (int p = 0; p < 4; p++) {
            unpack2(accs[p], lo, hi);
            int u0 = ub + 2 * p;
            if (u0 < Vv)     v_s[c * VPAD + u0]     = lo + bb;
            if (u0 + 1 < Vv) v_s[c * VPAD + u0 + 1] = hi + bb;
        }
    }
    __syncthreads();

    // --- stage 2: z[hc, j] = sum_u v[c,u] * attn[h,u,j]  (fp32x2) ---
#pragma unroll
    for (int rep = 0; rep < 2; rep++) {
        int hc = tid + rep * 256;
        int h = hc >> 6;
        int cc = hc & 63;
        const float* abase = attn_s + h * Vv * APAD;
        u64 acc[12];
#pragma unroll
        for (int p = 0; p < 12; p++) acc[p] = 0;
        float a24 = 0.f;
#pragma unroll 5
        for (int u = 0; u < Vv; u++) {
            float vval = v_s[cc * VPAD + u];
            u64 v2 = pack2(vval);
            const float* ar = abase + u * APAD;
#pragma unroll
            for (int p4 = 0; p4 < 6; p4++) {
                u64 a0, a1;
                lds128_u64(a0, a1, ar + p4 * 4);
                acc[2 * p4]     = ffma2(v2, a0, acc[2 * p4]);
                acc[2 * p4 + 1] = ffma2(v2, a1, acc[2 * p4 + 1]);
            }
            a24 += vval * ar[24];
        }
        float* zr = z_s + hc * ZPAD;
#pragma unroll
        for (int p = 0; p < 12; p++) sts64(zr + 2 * p, acc[p]);
        zr[24] = a24;
    }
    __syncthreads();

    // --- stage 3: out[o,u] = sum_k Wo[o,k] * z[k,u], double-buffered 32-col chunks ---
    {
        const int o = tid;
        u64 acc[12];
#pragma unroll
        for (int p = 0; p < 12; p++) acc[p] = 0;
        float acc24 = 0.f;

        const float4* Wo4 = (const float4*)Wo;

        // prefetch chunk 0 into buffer 0
        {
            const float4* src = Wo4 + (size_t)tid * 128;
            float* dst = w_s + tid * W2PAD;
#pragma unroll
            for (int j = 0; j < 8; j++) {
                float4 wv = src[j];
                dst[4 * j + 0] = wv.x; dst[4 * j + 1] = wv.y;
                dst[4 * j + 2] = wv.z; dst[4 * j + 3] = wv.w;
            }
        }
        __syncthreads();

        for (int c = 0; c < 16; c++) {
            // prefetch next chunk into the other buffer
            if (c < 15) {
                const float4* src = Wo4 + (size_t)tid * 128 + (c + 1) * 8;
                float* dst = w_s + ((c + 1) & 1) * W2BUF + tid * W2PAD;
#pragma unroll
                for (int j = 0; j < 8; j++) {
                    float4 wv = src[j];
                    dst[4 * j + 0] = wv.x; dst[4 * j + 1] = wv.y;
                    dst[4 * j + 2] = wv.z; dst[4 * j + 3] = wv.w;
                }
            }
            const float* wb = w_s + (c & 1) * W2BUF + o * W2PAD;
            const float* zb = z_s + c * 32 * ZPAD;
#pragma unroll 8
            for (int kk = 0; kk < 32; kk++) {
                float w = wb[kk];
                u64 w2 = pack2(w);
                const float* zr = zb + kk * ZPAD;
#pragma unroll
                for (int p4 = 0; p4 < 6; p4++) {
                    u64 z0, z1;
                    lds128_u64(z0, z1, zr + p4 * 4);
                    acc[2 * p4]     = ffma2(w2, z0, acc[2 * p4]);
                    acc[2 * p4 + 1] = ffma2(w2, z1, acc[2 * p4 + 1]);
                }
                acc24 += w * zr[24];
            }
            __syncthreads();
        }

        // epilogue: + bo + residual feature
        float bb = bo[o];
        float* orow = out + ((size_t)(n * Cc + o) * Tt + t) * Vv;
        const float* frow = f_s + o * FPAD;
        float lo, hi;
#pragma unroll
        for (int p = 0; p < 12; p++) {
            unpack2(acc[p], lo, hi);
            orow[2 * p]     = lo + bb + frow[2 * p];
            orow[2 * p + 1] = hi + bb + frow[2 * p + 1];
        }
        orow[24] = acc24 + bb + frow[24];
    }
}

// ---------------------------------------------------------------------------
extern "C" void kernel_launch(void* const* d_in, const int* in_sizes, int n_in,
                              void* d_out, int out_size) {
    const float* feature = (const float*)d_in[0];
    const float* tf      = (const float*)d_in[1];
    const float* Wq      = (const float*)d_in[2];
    const float* bq      = (const float*)d_in[3];
    const float* Wk      = (const float*)d_in[4];
    const float* bk      = (const float*)d_in[5];
    const float* Wv      = (const float*)d_in[6];
    const float* bv      = (const float*)d_in[7];
    const float* Wo      = (const float*)d_in[8];
    const float* bo      = (const float*)d_in[9];
    float* out = (float*)d_out;

    const size_t qk_smem   = (size_t)HC * Vv * sizeof(float);      // 51200
    const size_t attn_smem = (size_t)2 * HC * Vv * sizeof(float);  // 102400
    const size_t wunion = 2 * W2BUF;                               // 16896 > 256*65
    const size_t main_smem = (size_t)(Cc * FPAD + Dd * VPAD + HC * ZPAD +
                                      Hh * Vv * APAD + wunion) * sizeof(float);

    cudaFuncSetAttribute((const void*)qk_kernel,
                         cudaFuncAttributeMaxDynamicSharedMemorySize, (int)qk_smem);
    cudaFuncSetAttribute((const void*)attn_kernel,
                         cudaFuncAttributeMaxDynamicSharedMemorySize, (int)attn_smem);
    cudaFuncSetAttribute((const void*)main_kernel,
                         cudaFuncAttributeMaxDynamicSharedMemorySize, (int)main_smem);

    qk_kernel<<<100, 256, qk_smem>>>(tf, Wq, bq, Wk, bk);
    attn_kernel<<<1, 256, attn_smem>>>();
    main_kernel<<<Nn * Tt, 256, main_smem>>>(feature, Wv, bv, Wo, bo, out);
}

// round 4
// speedup vs baseline: 4.6825x; 4.6825x over previous
#include <cuda_runtime.h>

// Problem constants
#define Nn 8
#define Cc 256
#define Tt 1024
#define Vv 25
#define Hh 8
#define Dd 64
#define HC 512   // Hh * Dd

// Precomputed small tensors (batch/time independent)
__device__ float g_q[HC * Vv];
__device__ float g_k[HC * Vv];
__device__ float g_attn[Hh * Vv * Vv];

// ---------------- helpers ----------------
__device__ __forceinline__ unsigned f2tf(float x) {
    unsigned r; asm("cvt.rna.tf32.f32 %0, %1;" : "=r"(r) : "f"(x)); return r;
}
__device__ __forceinline__ void mma8(float* c, unsigned a0, unsigned a1, unsigned a2,
                                     unsigned a3, unsigned b0, unsigned b1) {
    asm("mma.sync.aligned.m16n8k8.row.col.f32.tf32.tf32.f32 "
        "{%0,%1,%2,%3}, {%4,%5,%6,%7}, {%8,%9}, {%0,%1,%2,%3};"
        : "+f"(c[0]), "+f"(c[1]), "+f"(c[2]), "+f"(c[3])
        : "r"(a0), "r"(a1), "r"(a2), "r"(a3), "r"(b0), "r"(b1));
}
__device__ __forceinline__ void cpasync16(float* dst, const float* src) {
    unsigned d = (unsigned)__cvta_generic_to_shared(dst);
    asm volatile("cp.async.cg.shared.global [%0], [%1], 16;" :: "r"(d), "l"(src));
}
__device__ __forceinline__ unsigned fbits(float x) { return __float_as_uint(x); }
__device__ __forceinline__ float ubits(unsigned x) { return __uint_as_float(x); }

// ---------------------------------------------------------------------------
// Kernel 1: q = Wq @ tf + bq, k = Wk @ tf + bk
// ---------------------------------------------------------------------------
__global__ void qk_kernel(const float* __restrict__ tf,
                          const float* __restrict__ Wq, const float* __restrict__ bq,
                          const float* __restrict__ Wk, const float* __restrict__ bk) {
    extern __shared__ float tf_s[];
    for (int idx = threadIdx.x; idx < HC * Vv; idx += blockDim.x) tf_s[idx] = tf[idx];
    __syncthreads();

    int g = blockIdx.x * blockDim.x + threadIdx.x;
    int which = (g >= HC * Vv) ? 1 : 0;
    int r = which ? (g - HC * Vv) : g;
    int hc = r / Vv;
    int u = r - hc * Vv;
    const float* wrow = (which ? Wk : Wq) + hc * 512;
    float acc = which ? bk[hc] : bq[hc];
#pragma unroll 8
    for (int i = 0; i < 512; i++) acc += wrow[i] * tf_s[i * Vv + u];
    if (which) g_k[r] = acc; else g_q[r] = acc;
}

// ---------------------------------------------------------------------------
// Kernel 2: energy + softmax -> g_attn
// ---------------------------------------------------------------------------
__global__ void attn_kernel() {
    extern __shared__ float s[];
    float* q_s = s;
    float* k_s = s + HC * Vv;
    for (int idx = threadIdx.x; idx < HC * Vv; idx += blockDim.x) {
        q_s[idx] = g_q[idx];
        k_s[idx] = g_k[idx];
    }
    __syncthreads();

    int r = threadIdx.x;
    if (r < Hh * Vv) {
        int h = r / Vv;
        int u = r - h * Vv;
        float e[Vv];
#pragma unroll
        for (int j = 0; j < Vv; j++) e[j] = 0.f;
        const float* qb = q_s + h * Dd * Vv;
        const float* kb = k_s + h * Dd * Vv;
        for (int c = 0; c < Dd; c++) {
            float qv = qb[c * Vv + u];
#pragma unroll
            for (int j = 0; j < Vv; j++) e[j] += qv * kb[c * Vv + j];
        }
        float m = -1e30f;
#pragma unroll
        for (int j = 0; j < Vv; j++) { e[j] *= 0.125f; m = fmaxf(m, e[j]); }
        float ssum = 0.f;
#pragma unroll
        for (int j = 0; j < Vv; j++) { e[j] = expf(e[j] - m); ssum += e[j]; }
        float inv = 1.f / ssum;
        float* arow = g_attn + (h * Vv + u) * Vv;
#pragma unroll
        for (int j = 0; j < Vv; j++) arow[j] = e[j] * inv;
    }
}

// ---------------------------------------------------------------------------
// Kernel 3: fully-fused tf32 tensor-core kernel.
// One block = 256 threads = 8 warps, handles columns [ct*100, ct*100+100) of
// batch n (100 cols = 4 t's x 25 v).
//
// SMEM float offsets:
//   F_s  [64][104]  @0      (fp32 F K-chunk; b-operand of V-stage)
//   Wv_s [64][68]   @6656   (tf32)
//   V_s  [64][132]  @11008  (tf32, layout [c][tl*32+u], u>=25 zero)
//   Z_s  [104][68]  @19456  (tf32, col-major [col][c])
//   AT_s [8][32][36]@26528  (tf32, attn^T padded: [h][v][u])
//   Wo_s [256][68]  @35744  (fp32 raw; cvt at a-frag load)
//   bv_s 64 @53152, bo_s 256 @53216   -> total 53472 floats = 213888 B
// ---------------------------------------------------------------------------
#define FS_OFF  0
#define WVS_OFF 6656
#define VS_OFF  11008
#define ZS_OFF  19456
#define ATS_OFF 26528
#define WOS_OFF 35744
#define BVS_OFF 53152
#define BOS_OFF 53216
#define SMEM_FLOATS 53472

__global__ void __launch_bounds__(256, 1)
main_kernel(const float* __restrict__ f, const float* __restrict__ Wv,
            const float* __restrict__ bv, const float* __restrict__ Wo,
            const float* __restrict__ bo, float* __restrict__ out) {
    extern __shared__ float s[];
    float* F_s  = s + FS_OFF;
    float* Wv_s = s + WVS_OFF;
    float* V_s  = s + VS_OFF;
    float* Z_s  = s + ZS_OFF;
    float* AT_s = s + ATS_OFF;
    float* Wo_s = s + WOS_OFF;
    float* bv_s = s + BVS_OFF;
    float* bo_s = s + BOS_OFF;

    const int tid  = threadIdx.x;
    const int lane = tid & 31;
    const int wid  = tid >> 5;
    const int bI   = blockIdx.x;
    const int n    = bI >> 8;
    const int ct   = bI & 255;

    // ---- init: zero padded regions, load biases ----
    for (int i = tid; i < 8448; i += 256) V_s[i] = 0.f;
    for (int i = tid; i < 7072; i += 256) Z_s[i] = 0.f;
    for (int i = tid; i < 9216; i += 256) AT_s[i] = 0.f;
    if (tid < 64) bv_s[tid] = bv[tid];
    bo_s[tid] = bo[tid];
    {   // F pad cols 100..103
        int r = tid >> 2, c = tid & 3;
        F_s[r * 104 + 100 + c] = 0.f;
    }
    __syncthreads();
    // attn^T (tf32) fill: AT[h][v][u] = attn[h][u][v]
    for (int idx = tid; idx < Hh * Vv * Vv; idx += 256) {
        int h = idx / 625, rem = idx - h * 625;
        int u = rem / 25, v = rem - u * 25;
        AT_s[h * 1152 + v * 36 + u] = ubits(f2tf(g_attn[idx]));
    }

    // ================= Stage V: V = Wv @ F + bv (tf32 mma) =================
    const int v_mt  = wid & 3;          // m-tile (16 rows each, M=64)
    const int v_nt0 = (wid >> 2) ? 7 : 0;
    float vacc[7][4];
#pragma unroll
    for (int i = 0; i < 7; i++)
#pragma unroll
        for (int j = 0; j < 4; j++) vacc[i][j] = 0.f;

    const float4* f4base = (const float4*)(f + (size_t)n * 6553600 + (size_t)ct * 100);

    for (int kc = 0; kc < 4; kc++) {
        // load F chunk rows kc*64..kc*64+63, 100 floats each (25 float4)
        for (int idx4 = tid; idx4 < 1600; idx4 += 256) {
            int r = idx4 / 25, q = idx4 - r * 25;
            float4 v4 = f4base[((size_t)(kc * 64 + r) * 25600) / 4 + q];
            *(float4*)(F_s + r * 104 + q * 4) = v4;
        }
        // load Wv chunk (tf32-rounded)
        for (int idx4 = tid; idx4 < 1024; idx4 += 256) {
            int r = idx4 >> 4, j = idx4 & 15;
            float4 v4 = *(const float4*)(Wv + r * 256 + kc * 64 + j * 4);
            float4 o4;
            o4.x = ubits(f2tf(v4.x)); o4.y = ubits(f2tf(v4.y));
            o4.z = ubits(f2tf(v4.z)); o4.w = ubits(f2tf(v4.w));
            *(float4*)(Wv_s + r * 68 + j * 4) = o4;
        }
        __syncthreads();
#pragma unroll
        for (int ks = 0; ks < 8; ks++) {
            int k = ks * 8;
            const float* wvb = Wv_s + (v_mt * 16 + (lane >> 2)) * 68 + k + (lane & 3);
            unsigned a0 = fbits(wvb[0]),      a1 = fbits(wvb[8 * 68]);
            unsigned a2 = fbits(wvb[4]),      a3 = fbits(wvb[8 * 68 + 4]);
#pragma unroll
            for (int i = 0; i < 7; i++) {
                int nt = v_nt0 + i;
                const float* fb = F_s + (k + (lane & 3)) * 104 + nt * 8 + (lane >> 2);
                unsigned b0 = f2tf(fb[0]), b1 = f2tf(fb[4 * 104]);
                mma8(vacc[i], a0, a1, a2, a3, b0, b1);
            }
        }
        __syncthreads();
    }
    // V epilogue -> V_s (tf32, remapped [c][tl*32+u])
    {
        int r0 = v_mt * 16 + (lane >> 2);
        float bv0 = bv_s[r0], bv1 = bv_s[r0 + 8];
#pragma unroll
        for (int i = 0; i < 7; i++) {
            int nt = v_nt0 + i;
            int col0 = nt * 8 + (lane & 3) * 2;
            if (col0 < 100) {
                int tl = col0 / 25, u = col0 - tl * 25;
                V_s[r0 * 132 + tl * 32 + u]       = ubits(f2tf(vacc[i][0] + bv0));
                V_s[(r0 + 8) * 132 + tl * 32 + u] = ubits(f2tf(vacc[i][2] + bv1));
            }
            int c1 = col0 + 1;
            if (c1 < 100) {
                int tl = c1 / 25, u = c1 - tl * 25;
                V_s[r0 * 132 + tl * 32 + u]       = ubits(f2tf(vacc[i][1] + bv0));
                V_s[(r0 + 8) * 132 + tl * 32 + u] = ubits(f2tf(vacc[i][3] + bv1));
            }
        }
    }
    __syncthreads();

    // ================= Head loop: Z-gen + main mma =================
    const int z_tl = wid & 3;     // t-local for Z-gen
    const int z_mh = wid >> 2;    // c-half for Z-gen
    float macc[2][13][4];
#pragma unroll
    for (int mi = 0; mi < 2; mi++)
#pragma unroll
        for (int nt = 0; nt < 13; nt++)
#pragma unroll
            for (int j = 0; j < 4; j++) macc[mi][nt][j] = 0.f;

    for (int h = 0; h < 8; h++) {
        __syncthreads();  // prior readers of Z_s / Wo_s done

        // prefetch Wo chunk [256][64] via cp.async (raw fp32)
        for (int idx4 = tid; idx4 < 4096; idx4 += 256) {
            int o = idx4 >> 4, j = idx4 & 15;
            cpasync16(Wo_s + o * 68 + j * 4, Wo + o * 512 + h * 64 + j * 4);
        }
        asm volatile("cp.async.commit_group;");

        // ---- Z-gen mma: Z_t[64c, 25v] = V_t[64c, 25u] @ attn_h[25u, 25v] ----
        float zacc[2][4][4];
#pragma unroll
        for (int mi = 0; mi < 2; mi++)
#pragma unroll
            for (int nt = 0; nt < 4; nt++)
#pragma unroll
                for (int j = 0; j < 4; j++) zacc[mi][nt][j] = 0.f;

#pragma unroll
        for (int ks = 0; ks < 4; ks++) {
            int k = ks * 8;
#pragma unroll
            for (int mi = 0; mi < 2; mi++) {
                const float* vb = V_s + (z_mh * 32 + mi * 16 + (lane >> 2)) * 132
                                  + z_tl * 32 + k + (lane & 3);
                unsigned a0 = fbits(vb[0]),  a1 = fbits(vb[8 * 132]);
                unsigned a2 = fbits(vb[4]),  a3 = fbits(vb[8 * 132 + 4]);
#pragma unroll
                for (int nt = 0; nt < 4; nt++) {
                    const float* ab = AT_s + h * 1152 + (nt * 8 + (lane >> 2)) * 36
                                      + k + (lane & 3);
                    mma8(zacc[mi][nt], a0, a1, a2, a3, fbits(ab[0]), fbits(ab[4]));
                }
            }
        }
        // store Z (tf32, col-major [col][c])
#pragma unroll
        for (int mi = 0; mi < 2; mi++) {
            int r0 = z_mh * 32 + mi * 16 + (lane >> 2);
#pragma unroll
            for (int nt = 0; nt < 4; nt++) {
                int v0 = nt * 8 + (lane & 3) * 2;
                if (v0 < 25) {
                    int zc = (z_tl * 25 + v0) * 68;
                    Z_s[zc + r0]     = ubits(f2tf(zacc[mi][nt][0]));
                    Z_s[zc + r0 + 8] = ubits(f2tf(zacc[mi][nt][2]));
                }
                if (v0 + 1 < 25) {
                    int zc = (z_tl * 25 + v0 + 1) * 68;
                    Z_s[zc + r0]     = ubits(f2tf(zacc[mi][nt][1]));
                    Z_s[zc + r0 + 8] = ubits(f2tf(zacc[mi][nt][3]));
                }
            }
        }
        asm volatile("cp.async.wait_group 0;" ::: "memory");
        __syncthreads();  // Wo_s and Z_s ready

        // ---- main mma: acc[256,104] += Wo_h[256,64] @ Z[64,104] ----
#pragma unroll
        for (int ks = 0; ks < 8; ks++) {
            int k = ks * 8;
            unsigned bz[13][2];
#pragma unroll
            for (int nt = 0; nt < 13; nt++) {
                const float* zb = Z_s + (nt * 8 + (lane >> 2)) * 68 + k + (lane & 3);
                bz[nt][0] = fbits(zb[0]);
                bz[nt][1] = fbits(zb[4]);
            }
#pragma unroll
            for (int mi = 0; mi < 2; mi++) {
                const float* wb = Wo_s + (wid * 32 + mi * 16 + (lane >> 2)) * 68
                                  + k + (lane & 3);
                unsigned a0 = f2tf(wb[0]), a1 = f2tf(wb[8 * 68]);
                unsigned a2 = f2tf(wb[4]), a3 = f2tf(wb[8 * 68 + 4]);
#pragma unroll
                for (int nt = 0; nt < 13; nt++)
                    mma8(macc[mi][nt], a0, a1, a2, a3, bz[nt][0], bz[nt][1]);
            }
        }
    }

    // ================= Epilogue: + bo + residual f =================
    {
        const size_t base = (size_t)n * 6553600 + (size_t)ct * 100;
#pragma unroll
        for (int mi = 0; mi < 2; mi++) {
            int r0 = wid * 32 + mi * 16 + (lane >> 2);
            float bo0 = bo_s[r0], bo1 = bo_s[r0 + 8];
#pragma unroll
            for (int nt = 0; nt < 13; nt++) {
                int col0 = nt * 8 + (lane & 3) * 2;
                if (col0 < 100) {
                    size_t a0 = base + (size_t)r0 * 25600 + col0;
                    size_t a2 = base + (size_t)(r0 + 8) * 25600 + col0;
                    out[a0] = macc[mi][nt][0] + bo0 + __ldg(f + a0);
                    out[a2] = macc[mi][nt][2] + bo1 + __ldg(f + a2);
                }
                int c1 = col0 + 1;
                if (c1 < 100) {
                    size_t a1 = base + (size_t)r0 * 25600 + c1;
                    size_t a3 = base + (size_t)(r0 + 8) * 25600 + c1;
                    out[a1] = macc[mi][nt][1] + bo0 + __ldg(f + a1);
                    out[a3] = macc[mi][nt][3] + bo1 + __ldg(f + a3);
                }
            }
        }
    }
}

// ---------------------------------------------------------------------------
extern "C" void kernel_launch(void* const* d_in, const int* in_sizes, int n_in,
                              void* d_out, int out_size) {
    const float* feature = (const float*)d_in[0];
    const float* tf      = (const float*)d_in[1];
    const float* Wq      = (const float*)d_in[2];
    const float* bq      = (const float*)d_in[3];
    const float* Wk      = (const float*)d_in[4];
    const float* bk      = (const float*)d_in[5];
    const float* Wv      = (const float*)d_in[6];
    const float* bv      = (const float*)d_in[7];
    const float* Wo      = (const float*)d_in[8];
    const float* bo      = (const float*)d_in[9];
    float* out = (float*)d_out;

    const size_t qk_smem   = (size_t)HC * Vv * sizeof(float);
    const size_t attn_smem = (size_t)2 * HC * Vv * sizeof(float);
    const size_t main_smem = (size_t)SMEM_FLOATS * sizeof(float);  // 213888 B

    cudaFuncSetAttribute((const void*)qk_kernel,
                         cudaFuncAttributeMaxDynamicSharedMemorySize, (int)qk_smem);
    cudaFuncSetAttribute((const void*)attn_kernel,
                         cudaFuncAttributeMaxDynamicSharedMemorySize, (int)attn_smem);
    cudaFuncSetAttribute((const void*)main_kernel,
                         cudaFuncAttributeMaxDynamicSharedMemorySize, (int)main_smem);

    qk_kernel<<<100, 256, qk_smem>>>(tf, Wq, bq, Wk, bk);
    attn_kernel<<<1, 256, attn_smem>>>();
    main_kernel<<<Nn * 256, 256, main_smem>>>(feature, Wv, bv, Wo, bo, out);
}